// round 5
// baseline (speedup 1.0000x reference)
#include <cuda_runtime.h>
#include <math.h>

#define B_  64
#define T_  512
#define I_  1024
#define H_  1024
#define M_  (B_*T_)

typedef unsigned long long ull;

// ---------------------------------------------------------------------------
// f32x2 packed-FMA helpers (sm_103a FFMA2 — only reachable via PTX)
// ---------------------------------------------------------------------------
__device__ __forceinline__ ull ffma2(ull a, ull b, ull c) {
    ull d;
    asm("fma.rn.f32x2 %0, %1, %2, %3;" : "=l"(d) : "l"(a), "l"(b), "l"(c));
    return d;
}
__device__ __forceinline__ ull splat2(float x) {
    ull r;
    asm("mov.b64 %0, {%1, %1};" : "=l"(r) : "f"(x));
    return r;
}
__device__ __forceinline__ float2 unpack2(ull v) {
    float2 f;
    asm("mov.b64 {%0, %1}, %2;" : "=f"(f.x), "=f"(f.y) : "l"(v));
    return f;
}

// ---------------------------------------------------------------------------
// Scratch (device globals — no allocation allowed)
// ---------------------------------------------------------------------------
__device__ float g_h[2][B_*H_];            // h3 double buffer
__device__ unsigned g_cnt[2];              // per-batch-half barrier counters
__device__ volatile unsigned g_gen[2];     // monotonic generations (wrap-safe,
                                           // snapshot-based -> replay-safe)
#define SCAN_BLOCKS  128
#define GROUP_BLOCKS 64   // blocks per batch-half barrier group

// ---------------------------------------------------------------------------
// Kernel A: xw = x @ W^T + bW  -> out1 region of d_out
// 128x128x16 tile, 256 threads, 8x8 micro-tile as 4 m-pairs x 8 n in FFMA2
// (acc pair spans adjacent m rows; b splat per (n,k), amortized over 4 FFMA2).
// ---------------------------------------------------------------------------
#define BM 128
#define BN 128
#define BK 16
#define AST 132   // padded stride; (132*4)%16==0 keeps float4 alignment

__global__ __launch_bounds__(256, 2)
void xw_gemm_kernel(const float* __restrict__ X, const float* __restrict__ W,
                    const float* __restrict__ bW, float* __restrict__ C) {
    __shared__ float As[BK * AST];   // As[k][m]
    __shared__ float Bs[BK * AST];   // Bs[k][n]

    const int tid = threadIdx.x;
    const int tx  = tid & 15;        // 8 cols each
    const int ty  = tid >> 4;        // 8 rows each (as 4 pairs)
    const int m0  = blockIdx.y * BM;
    const int n0  = blockIdx.x * BN;
    const int r   = tid >> 2;        // 0..63 (staging row)
    const int c4  = (tid & 3) * 4;   // 0,4,8,12 (staging k)

    ull acc[4][8];
#pragma unroll
    for (int i = 0; i < 4; ++i)
#pragma unroll
        for (int j = 0; j < 8; ++j) acc[i][j] = 0ull;

    for (int k0 = 0; k0 < I_; k0 += BK) {
        // issue all 4 tile loads first (MLP), then sync+store
        float4 av0 = *(const float4*)&X[(size_t)(m0 + r     ) * I_ + k0 + c4];
        float4 av1 = *(const float4*)&X[(size_t)(m0 + r + 64) * I_ + k0 + c4];
        float4 bv0 = *(const float4*)&W[(size_t)(n0 + r     ) * I_ + k0 + c4];
        float4 bv1 = *(const float4*)&W[(size_t)(n0 + r + 64) * I_ + k0 + c4];
        __syncthreads();   // previous compute done reading smem
        As[(c4 + 0) * AST + r] = av0.x;  As[(c4 + 1) * AST + r] = av0.y;
        As[(c4 + 2) * AST + r] = av0.z;  As[(c4 + 3) * AST + r] = av0.w;
        As[(c4 + 0) * AST + r + 64] = av1.x;  As[(c4 + 1) * AST + r + 64] = av1.y;
        As[(c4 + 2) * AST + r + 64] = av1.z;  As[(c4 + 3) * AST + r + 64] = av1.w;
        Bs[(c4 + 0) * AST + r] = bv0.x;  Bs[(c4 + 1) * AST + r] = bv0.y;
        Bs[(c4 + 2) * AST + r] = bv0.z;  Bs[(c4 + 3) * AST + r] = bv0.w;
        Bs[(c4 + 0) * AST + r + 64] = bv1.x;  Bs[(c4 + 1) * AST + r + 64] = bv1.y;
        Bs[(c4 + 2) * AST + r + 64] = bv1.z;  Bs[(c4 + 3) * AST + r + 64] = bv1.w;
        __syncthreads();

#pragma unroll
        for (int kk = 0; kk < BK; ++kk) {
            const ulonglong2* ap = (const ulonglong2*)&As[kk * AST + ty * 8];
            ulonglong2 aA = ap[0];          // m-pairs (0,1),(2,3)
            ulonglong2 aB = ap[1];          // m-pairs (4,5),(6,7)
            const float* bp = &Bs[kk * AST + tx * 8];
            float4 b0 = *(const float4*)bp;
            float4 b1 = *(const float4*)(bp + 4);
            float bf[8] = {b0.x, b0.y, b0.z, b0.w, b1.x, b1.y, b1.z, b1.w};
#pragma unroll
            for (int j = 0; j < 8; ++j) {
                ull s = splat2(bf[j]);
                acc[0][j] = ffma2(aA.x, s, acc[0][j]);
                acc[1][j] = ffma2(aA.y, s, acc[1][j]);
                acc[2][j] = ffma2(aB.x, s, acc[2][j]);
                acc[3][j] = ffma2(aB.y, s, acc[3][j]);
            }
        }
    }

    float bb[8];
#pragma unroll
    for (int j = 0; j < 8; ++j) bb[j] = bW[n0 + tx * 8 + j];

#pragma unroll
    for (int i = 0; i < 4; ++i) {
        float lo[8], hi[8];
#pragma unroll
        for (int j = 0; j < 8; ++j) {
            float2 f = unpack2(acc[i][j]);
            lo[j] = f.x + bb[j];
            hi[j] = f.y + bb[j];
        }
        size_t row0 = (size_t)(m0 + ty * 8 + 2 * i) * H_ + n0 + tx * 8;
        *(float4*)&C[row0]           = make_float4(lo[0], lo[1], lo[2], lo[3]);
        *(float4*)&C[row0 + 4]       = make_float4(lo[4], lo[5], lo[6], lo[7]);
        *(float4*)&C[row0 + H_]      = make_float4(hi[0], hi[1], hi[2], hi[3]);
        *(float4*)&C[row0 + H_ + 4]  = make_float4(hi[4], hi[5], hi[6], hi[7]);
    }
}

// ---------------------------------------------------------------------------
// Kernel B: persistent scan. 128 blocks x 256 threads, 1 block/SM (forced by
// 192KB smem; 128 <= 148 SMs -> all co-resident, software barrier safe).
// Block (bh, cg): batches [bh*32,+32), cols [cg*16,+16). Warp w -> cols
// (2w, 2w+1), lane l -> batch bh*32+l.
// - U slice (16x1024, 64KB) resident in smem all 512 steps.
// - h staged per step as float4 with 16B-granule XOR swizzle (k4 ^ (l&7)):
//   conflict-free STS.128 staging AND LDS.128 compute loads (per 8-lane
//   phase, c=0..7 covers all 8 bank groups).
// - Inner loop in FFMA2: acc pairs split over k-parity so every operand pair
//   is register-adjacent from LDS.128 (zero packing movs).
// - Two independent 64-block barrier groups (batch halves are disjoint);
//   arrive/wait split so xw prefetch + out stores hide arrival skew.
// ---------------------------------------------------------------------------
#define USH_FLOATS (16 * 1024)
#define HSH_FLOATS (32 * 1024)
#define SCAN_SMEM  ((USH_FLOATS + HSH_FLOATS) * sizeof(float))

__global__ __launch_bounds__(256, 1)
void scan_kernel(float* __restrict__ out, const float* __restrict__ U,
                 const float* __restrict__ bU) {
    extern __shared__ float smem[];
    float*  U_sh = smem;                           // [16][1024]
    float4* h_sh = (float4*)(smem + USH_FLOATS);   // 32*256 granules, swizzled

    const int tid = threadIdx.x;
    const int l   = tid & 31;
    const int w   = tid >> 5;            // 0..7
    const int bh  = blockIdx.x & 1;
    const int cg  = blockIdx.x >> 1;     // 0..63
    const int b   = bh * 32 + l;
    const int n0  = cg * 16 + 2 * w;

    // U slice -> shared (float4-coalesced), once
    {
        const float4* Us = (const float4*)(U + (size_t)cg * 16 * H_);
        float4* Ud = (float4*)U_sh;
#pragma unroll
        for (int i = tid; i < 16 * 256; i += 256) Ud[i] = Us[i];
    }
    const float bU0 = bU[n0];
    const float bU1 = bU[n0 + 1];
    __syncthreads();

    float* o_row = out + (size_t)b * T_ * H_;

    // tau = 0: h3 = tanh(xw)
    {
        float2 xw = *(const float2*)(o_row + n0);
        float h0 = tanhf(xw.x), h1 = tanhf(xw.y);
        *(float2*)(o_row + n0) = make_float2(h0, h1);
        *(float2*)(&g_h[0][(size_t)b * H_ + n0]) = make_float2(h0, h1);
    }

    unsigned my_gen = 0;
    // arrive (barrier for step 1)
    __syncthreads();
    if (tid == 0) {
        __threadfence();
        my_gen = g_gen[bh];
        if (atomicAdd(&g_cnt[bh], 1u) == GROUP_BLOCKS - 1) {
            atomicExch(&g_cnt[bh], 0u);
            __threadfence();
            g_gen[bh] = my_gen + 1;
        }
    }

    const ulonglong2* u0p = (const ulonglong2*)(U_sh + (size_t)(2 * w) * H_);
    const ulonglong2* u1p = u0p + 256;
    const ulonglong2* hb  = (const ulonglong2*)h_sh + l * 256;
    const int c = l & 7;

    for (int tau = 1; tau < T_; ++tau) {
        // xw prefetch: only this thread ever touches this element after
        // kernel A; independent of the barrier -> overlaps the spin.
        float2 xw = __ldcg((const float2*)(o_row + (size_t)tau * H_ + n0));

        // wait (tid 0 spins; light backoff keeps L2 poll pressure low)
        if (tid == 0) {
            while (g_gen[bh] == my_gen) { __nanosleep(64); }
            __threadfence();
        }
        __syncthreads();

        // stage prev h (my 32 batches) into swizzled shared; __ldcg dodges
        // L1 lines stale from two steps ago (same buffer).
        {
            const float4* src = (const float4*)(g_h[(tau - 1) & 1] +
                                                (size_t)bh * 32 * H_);
#pragma unroll 8
            for (int s = 0; s < 32; ++s)
                h_sh[s * 256 + (tid ^ (s & 7))] = __ldcg(src + s * 256 + tid);
        }
        __syncthreads();

        // matvec: acc pairs split over k-parity -> pure FFMA2, no movs
        ull a0a = 0ull, a0b = 0ull, a1a = 0ull, a1b = 0ull;
#pragma unroll 8
        for (int k4 = 0; k4 < 256; ++k4) {
            ulonglong2 u0 = u0p[k4];          // warp-uniform broadcast
            ulonglong2 u1 = u1p[k4];          // warp-uniform broadcast
            ulonglong2 hv = hb[k4 ^ c];       // conflict-free LDS.128
            a0a = ffma2(hv.x, u0.x, a0a);
            a0b = ffma2(hv.y, u0.y, a0b);
            a1a = ffma2(hv.x, u1.x, a1a);
            a1b = ffma2(hv.y, u1.y, a1b);
        }
        float2 p0a = unpack2(a0a), p0b = unpack2(a0b);
        float2 p1a = unpack2(a1a), p1b = unpack2(a1b);
        float acc0 = (p0a.x + p0a.y) + (p0b.x + p0b.y);
        float acc1 = (p1a.x + p1a.y) + (p1b.x + p1b.y);

        float h0 = tanhf(xw.x + acc0 + bU0);
        float h1 = tanhf(xw.y + acc1 + bU1);

        *(float2*)(o_row + (size_t)tau * H_ + n0) = make_float2(h0, h1);
        if (tau < T_ - 1) {
            *(float2*)(&g_h[tau & 1][(size_t)b * H_ + n0]) = make_float2(h0, h1);
            // arrive for step tau+1
            __syncthreads();
            if (tid == 0) {
                __threadfence();
                my_gen = g_gen[bh];
                if (atomicAdd(&g_cnt[bh], 1u) == GROUP_BLOCKS - 1) {
                    atomicExch(&g_cnt[bh], 0u);
                    __threadfence();
                    g_gen[bh] = my_gen + 1;
                }
            }
        } else {
            // out2 = out1[:, -1, :]
            *(float2*)(out + (size_t)M_ * H_ + (size_t)b * H_ + n0) =
                make_float2(h0, h1);
        }
    }
}

// ---------------------------------------------------------------------------
// Launch
// ---------------------------------------------------------------------------
extern "C" void kernel_launch(void* const* d_in, const int* in_sizes, int n_in,
                              void* d_out, int out_size) {
    const float* x  = (const float*)d_in[0];   // [B,T,I]
    const float* W  = (const float*)d_in[1];   // [H,I]
    const float* bW = (const float*)d_in[2];   // [H]
    const float* U  = (const float*)d_in[3];   // [H,H]
    const float* bU = (const float*)d_in[4];   // [H]
    float* out = (float*)d_out;                // out1 [B*T*H] ++ out2 [B*H]

    dim3 gA(H_ / BN, M_ / BM);   // (8, 256)
    xw_gemm_kernel<<<gA, 256>>>(x, W, bW, out);

    cudaFuncSetAttribute(scan_kernel, cudaFuncAttributeMaxDynamicSharedMemorySize,
                         (int)SCAN_SMEM);
    scan_kernel<<<SCAN_BLOCKS, 256, SCAN_SMEM>>>(out, U, bU);
}

// round 8
// speedup vs baseline: 1.6732x; 1.6732x over previous
#include <cuda_runtime.h>
#include <math.h>

#define B_  64
#define T_  512
#define I_  1024
#define H_  1024
#define M_  (B_*T_)

typedef unsigned long long ull;

// ---------------------------------------------------------------------------
// f32x2 packed helpers (sm_103a FFMA2/FADD2 — only reachable via PTX)
// ---------------------------------------------------------------------------
__device__ __forceinline__ ull ffma2(ull a, ull b, ull c) {
    ull d;
    asm("fma.rn.f32x2 %0, %1, %2, %3;" : "=l"(d) : "l"(a), "l"(b), "l"(c));
    return d;
}
__device__ __forceinline__ ull fadd2(ull a, ull b) {
    ull d;
    asm("add.rn.f32x2 %0, %1, %2;" : "=l"(d) : "l"(a), "l"(b));
    return d;
}
__device__ __forceinline__ ull splat2(float x) {
    ull r;
    asm("mov.b64 %0, {%1, %1};" : "=l"(r) : "f"(x));
    return r;
}
__device__ __forceinline__ float2 unpack2(ull v) {
    float2 f;
    asm("mov.b64 {%0, %1}, %2;" : "=f"(f.x), "=f"(f.y) : "l"(v));
    return f;
}

// ---------------------------------------------------------------------------
// Scratch (device globals — no allocation allowed)
// ---------------------------------------------------------------------------
__device__ float g_ht[2][H_][B_];      // TRANSPOSED h double buffer: [buf][k][b]
__device__ unsigned g_cnt[2];          // per-batch-half barrier counters
__device__ volatile unsigned g_gen[2]; // monotonic generations (replay-safe)

#define SCAN_BLOCKS  128
#define GROUP_BLOCKS 64

// ---------------------------------------------------------------------------
// Kernel A: xw = x @ W^T + bW  -> out1 region of d_out (unchanged from R4)
// ---------------------------------------------------------------------------
#define BM 128
#define BN 128
#define BK 16
#define AST 132

__global__ __launch_bounds__(256, 2)
void xw_gemm_kernel(const float* __restrict__ X, const float* __restrict__ W,
                    const float* __restrict__ bW, float* __restrict__ C) {
    __shared__ float As[BK * AST];
    __shared__ float Bs[BK * AST];

    const int tid = threadIdx.x;
    const int tx  = tid & 15;
    const int ty  = tid >> 4;
    const int m0  = blockIdx.y * BM;
    const int n0  = blockIdx.x * BN;
    const int r   = tid >> 2;
    const int c4  = (tid & 3) * 4;

    ull acc[4][8];
#pragma unroll
    for (int i = 0; i < 4; ++i)
#pragma unroll
        for (int j = 0; j < 8; ++j) acc[i][j] = 0ull;

    for (int k0 = 0; k0 < I_; k0 += BK) {
        float4 av0 = *(const float4*)&X[(size_t)(m0 + r     ) * I_ + k0 + c4];
        float4 av1 = *(const float4*)&X[(size_t)(m0 + r + 64) * I_ + k0 + c4];
        float4 bv0 = *(const float4*)&W[(size_t)(n0 + r     ) * I_ + k0 + c4];
        float4 bv1 = *(const float4*)&W[(size_t)(n0 + r + 64) * I_ + k0 + c4];
        __syncthreads();
        As[(c4 + 0) * AST + r] = av0.x;  As[(c4 + 1) * AST + r] = av0.y;
        As[(c4 + 2) * AST + r] = av0.z;  As[(c4 + 3) * AST + r] = av0.w;
        As[(c4 + 0) * AST + r + 64] = av1.x;  As[(c4 + 1) * AST + r + 64] = av1.y;
        As[(c4 + 2) * AST + r + 64] = av1.z;  As[(c4 + 3) * AST + r + 64] = av1.w;
        Bs[(c4 + 0) * AST + r] = bv0.x;  Bs[(c4 + 1) * AST + r] = bv0.y;
        Bs[(c4 + 2) * AST + r] = bv0.z;  Bs[(c4 + 3) * AST + r] = bv0.w;
        Bs[(c4 + 0) * AST + r + 64] = bv1.x;  Bs[(c4 + 1) * AST + r + 64] = bv1.y;
        Bs[(c4 + 2) * AST + r + 64] = bv1.z;  Bs[(c4 + 3) * AST + r + 64] = bv1.w;
        __syncthreads();

#pragma unroll
        for (int kk = 0; kk < BK; ++kk) {
            const ulonglong2* ap = (const ulonglong2*)&As[kk * AST + ty * 8];
            ulonglong2 aA = ap[0];
            ulonglong2 aB = ap[1];
            const float* bp = &Bs[kk * AST + tx * 8];
            float4 b0 = *(const float4*)bp;
            float4 b1 = *(const float4*)(bp + 4);
            float bf[8] = {b0.x, b0.y, b0.z, b0.w, b1.x, b1.y, b1.z, b1.w};
#pragma unroll
            for (int j = 0; j < 8; ++j) {
                ull s = splat2(bf[j]);
                acc[0][j] = ffma2(aA.x, s, acc[0][j]);
                acc[1][j] = ffma2(aA.y, s, acc[1][j]);
                acc[2][j] = ffma2(aB.x, s, acc[2][j]);
                acc[3][j] = ffma2(aB.y, s, acc[3][j]);
            }
        }
    }

    float bb[8];
#pragma unroll
    for (int j = 0; j < 8; ++j) bb[j] = bW[n0 + tx * 8 + j];

#pragma unroll
    for (int i = 0; i < 4; ++i) {
        float lo[8], hi[8];
#pragma unroll
        for (int j = 0; j < 8; ++j) {
            float2 f = unpack2(acc[i][j]);
            lo[j] = f.x + bb[j];
            hi[j] = f.y + bb[j];
        }
        size_t row0 = (size_t)(m0 + ty * 8 + 2 * i) * H_ + n0 + tx * 8;
        *(float4*)&C[row0]           = make_float4(lo[0], lo[1], lo[2], lo[3]);
        *(float4*)&C[row0 + 4]       = make_float4(lo[4], lo[5], lo[6], lo[7]);
        *(float4*)&C[row0 + H_]      = make_float4(hi[0], hi[1], hi[2], hi[3]);
        *(float4*)&C[row0 + H_ + 4]  = make_float4(hi[4], hi[5], hi[6], hi[7]);
    }
}

// ---------------------------------------------------------------------------
// Kernel B: persistent scan, register-blocked step-GEMM (1 B/FMA).
// 128 blocks x 256 threads. Block (bh, cg): batches [bh*32,+32), cols
// [cg*16,+16). Warp w: k in [w*128,+128). Lane l = k4*8 + cgl*4 + bg:
//   k4  (l>>3)    : 4-way k split within warp (32 k each)
//   cgl ((l>>2)&1): col half -> 8 cols
//   bg  (l&3)     : batch group -> 8 batches (4 f32x2 pairs)
// Lane register tile: 8 batches x 8 cols = 32 f32x2 accumulators.
// h read directly from g_ht (transposed, L2-resident) via __ldcg.
// U transposed in smem ([k][16], stride 20).
// Reduce: 2-stage shfl butterfly (k4), then 8-way cross-warp via smem.
// ---------------------------------------------------------------------------
#define UT_STRIDE 20
#define UT_FLOATS (H_ * UT_STRIDE)                 // 20480 (80 KB)
#define RED_OFF   UT_FLOATS
#define RED_FLOATS (8 * 512)                       // 16 KB
#define XWS_OFF   (RED_OFF + RED_FLOATS)
#define CF_OFF    (XWS_OFF + 512)
#define SCAN_SMEM ((CF_OFF + 512) * sizeof(float)) // ~86 KB

__global__ __launch_bounds__(256, 1)
void scan_kernel(float* __restrict__ out, const float* __restrict__ U,
                 const float* __restrict__ bU) {
    extern __shared__ float smem[];
    float* U_t  = smem;              // [1024][20] (16 used)
    float* red  = smem + RED_OFF;    // [8][16*32]  [w][c*32+b]
    float* xw_s = smem + XWS_OFF;    // [16][32]
    float* C_f  = smem + CF_OFF;     // [16][32]

    const int tid = threadIdx.x;
    const int l   = tid & 31;
    const int w   = tid >> 5;
    const int bh  = blockIdx.x & 1;
    const int cg  = blockIdx.x >> 1;          // 0..63
    const int k4  = l >> 3;
    const int cgl = (l >> 2) & 1;
    const int bg  = l & 3;
    const int kbase = w * 128 + k4 * 32;

    // epilogue mappings
    const int c7 = tid >> 4;                  // 0..15
    const int b7 = (tid & 15) * 2;            // 0..30
    const int b9 = tid >> 3;                  // 0..31
    const int c9 = (tid & 7) * 2;             // 0..14

    // U transpose -> smem (one-time): U[n][k] -> U_t[k][c]
    for (int idx = tid; idx < 16 * H_; idx += 256) {
        int c = idx >> 10;
        int k = idx & (H_ - 1);
        U_t[k * UT_STRIDE + c] = U[(size_t)(cg * 16 + c) * H_ + k];
    }
    const float bUc = bU[cg * 16 + c7];
    __syncthreads();

    // tau = 0: h = tanh(xw[:,0,:])  (one-time, scattered is fine)
    {
        int n = cg * 16 + c7;
        int b0 = bh * 32 + b7;
        float x0 = out[(size_t)b0 * T_ * H_ + n];
        float x1 = out[(size_t)(b0 + 1) * T_ * H_ + n];
        float h0 = tanhf(x0), h1 = tanhf(x1);
        out[(size_t)b0 * T_ * H_ + n] = h0;
        out[(size_t)(b0 + 1) * T_ * H_ + n] = h1;
        *(float2*)&g_ht[0][n][b0] = make_float2(h0, h1);
    }

    unsigned my_gen = 0;
    __syncthreads();
    if (tid == 0) {
        __threadfence();
        my_gen = g_gen[bh];
        if (atomicAdd(&g_cnt[bh], 1u) == GROUP_BLOCKS - 1) {
            atomicExch(&g_cnt[bh], 0u);
            __threadfence();
            g_gen[bh] = my_gen + 1;
        }
    }

    const int n9 = cg * 16 + c9;
    const int bg9 = bh * 32 + b9;
    float* o9 = out + (size_t)bg9 * T_ * H_ + n9;          // out1[b9][.][c9]
    const float* urow0 = U_t + kbase * UT_STRIDE + cgl * 8;

    for (int tau = 1; tau < T_; ++tau) {
        // prefetch xw (own cols, written only by kernel A) — overlaps spin
        float2 xw = __ldcg((const float2*)(o9 + (size_t)tau * H_));

        // wait
        if (tid == 0) {
            while (g_gen[bh] == my_gen) { }
            __threadfence();
        }
        __syncthreads();

        // stash xw transposed for the epilogue
        xw_s[c9 * 32 + b9]       = xw.x;
        xw_s[(c9 + 1) * 32 + b9] = xw.y;

        // ---- register-blocked k-loop: 32 iters, 64 FMA per 64 B loaded ----
        const float* hrow = &g_ht[(tau - 1) & 1][kbase][bh * 32 + bg * 8];
        ull acc[8][4];
#pragma unroll
        for (int c = 0; c < 8; ++c)
#pragma unroll
            for (int p = 0; p < 4; ++p) acc[c][p] = 0ull;

#pragma unroll 8
        for (int i = 0; i < 32; ++i) {
            const ulonglong2* hp = (const ulonglong2*)(hrow + i * B_);
            ulonglong2 hA = __ldcg(hp);          // batches 0..3 (2 pairs)
            ulonglong2 hB = __ldcg(hp + 1);      // batches 4..7
            const float* up = urow0 + i * UT_STRIDE;
            float4 u0 = *(const float4*)up;
            float4 u1 = *(const float4*)(up + 4);
            float uf[8] = {u0.x, u0.y, u0.z, u0.w, u1.x, u1.y, u1.z, u1.w};
#pragma unroll
            for (int c = 0; c < 8; ++c) {
                ull s = splat2(uf[c]);
                acc[c][0] = ffma2(hA.x, s, acc[c][0]);
                acc[c][1] = ffma2(hA.y, s, acc[c][1]);
                acc[c][2] = ffma2(hB.x, s, acc[c][2]);
                acc[c][3] = ffma2(hB.y, s, acc[c][3]);
            }
        }

        // ---- in-warp reduction over k4 (lane bits 3,4) ----
#pragma unroll
        for (int c = 0; c < 8; ++c)
#pragma unroll
            for (int p = 0; p < 4; ++p) {
                acc[c][p] = fadd2(acc[c][p],
                                  __shfl_xor_sync(0xffffffffu, acc[c][p], 8));
                acc[c][p] = fadd2(acc[c][p],
                                  __shfl_xor_sync(0xffffffffu, acc[c][p], 16));
            }

        // ---- cross-warp partials to smem (k4==0 lanes only) ----
        if (l < 8) {
            float* rw = red + w * 512;
#pragma unroll
            for (int c = 0; c < 8; ++c)
#pragma unroll
                for (int p = 0; p < 4; ++p)
                    *(ull*)&rw[(cgl * 8 + c) * 32 + bg * 8 + 2 * p] = acc[c][p];
        }
        __syncthreads();

        // ---- final reduce + tanh + transposed h write ----
        {
            float s0 = 0.f, s1 = 0.f;
#pragma unroll
            for (int w8 = 0; w8 < 8; ++w8) {
                float2 v = *(const float2*)&red[w8 * 512 + c7 * 32 + b7];
                s0 += v.x;
                s1 += v.y;
            }
            float h0 = tanhf(xw_s[c7 * 32 + b7]     + s0 + bUc);
            float h1 = tanhf(xw_s[c7 * 32 + b7 + 1] + s1 + bUc);
            int n  = cg * 16 + c7;
            int b0 = bh * 32 + b7;
            *(float2*)&g_ht[tau & 1][n][b0] = make_float2(h0, h1);
            C_f[c7 * 32 + b7]     = h0;
            C_f[c7 * 32 + b7 + 1] = h1;
        }
        __syncthreads();   // C_f ready; also orders g_ht writes before arrive

        // ---- coalesced out1 (+out2) write ----
        float2 o = make_float2(C_f[c9 * 32 + b9], C_f[(c9 + 1) * 32 + b9]);
        *(float2*)(o9 + (size_t)tau * H_) = o;
        if (tau == T_ - 1)
            *(float2*)(out + (size_t)M_ * H_ + (size_t)bg9 * H_ + n9) = o;

        // ---- arrive for next step (g_ht stores ordered by sync above) ----
        if (tau < T_ - 1) {
            if (tid == 0) {
                __threadfence();
                my_gen = g_gen[bh];
                if (atomicAdd(&g_cnt[bh], 1u) == GROUP_BLOCKS - 1) {
                    atomicExch(&g_cnt[bh], 0u);
                    __threadfence();
                    g_gen[bh] = my_gen + 1;
                }
            }
        }
    }
}

// ---------------------------------------------------------------------------
// Launch
// ---------------------------------------------------------------------------
extern "C" void kernel_launch(void* const* d_in, const int* in_sizes, int n_in,
                              void* d_out, int out_size) {
    const float* x  = (const float*)d_in[0];   // [B,T,I]
    const float* W  = (const float*)d_in[1];   // [H,I]
    const float* bW = (const float*)d_in[2];   // [H]
    const float* U  = (const float*)d_in[3];   // [H,H]
    const float* bU = (const float*)d_in[4];   // [H]
    float* out = (float*)d_out;                // out1 [B*T*H] ++ out2 [B*H]

    dim3 gA(H_ / BN, M_ / BM);
    xw_gemm_kernel<<<gA, 256>>>(x, W, bW, out);

    cudaFuncSetAttribute(scan_kernel, cudaFuncAttributeMaxDynamicSharedMemorySize,
                         (int)SCAN_SMEM);
    scan_kernel<<<SCAN_BLOCKS, 256, SCAN_SMEM>>>(out, U, bU);
}

// round 9
// speedup vs baseline: 2.4530x; 1.4660x over previous
#include <cuda_runtime.h>
#include <math.h>

#define B_  64
#define T_  512
#define I_  1024
#define H_  1024
#define M_  (B_*T_)

typedef unsigned long long ull;

// ---------------------------------------------------------------------------
// f32x2 packed helpers (sm_103a FFMA2/FADD2 — only reachable via PTX)
// ---------------------------------------------------------------------------
__device__ __forceinline__ ull ffma2(ull a, ull b, ull c) {
    ull d;
    asm("fma.rn.f32x2 %0, %1, %2, %3;" : "=l"(d) : "l"(a), "l"(b), "l"(c));
    return d;
}
__device__ __forceinline__ ull fadd2(ull a, ull b) {
    ull d;
    asm("add.rn.f32x2 %0, %1, %2;" : "=l"(d) : "l"(a), "l"(b));
    return d;
}
__device__ __forceinline__ ull splat2(float x) {
    ull r;
    asm("mov.b64 %0, {%1, %1};" : "=l"(r) : "f"(x));
    return r;
}

// ---------------------------------------------------------------------------
// Scratch (device globals — no allocation allowed)
// ---------------------------------------------------------------------------
__device__ float g_xt[T_][I_][B_];     // transposed x: [t][k][b]  (128 MB)
__device__ float g_ht[2][H_][B_];      // transposed h double buffer [buf][k][b]
__device__ unsigned g_cnt[2];          // per-batch-half barrier counters
__device__ volatile unsigned g_gen[2]; // monotonic generations (replay-safe)

#define SCAN_BLOCKS  128
#define GROUP_BLOCKS 64

// ---------------------------------------------------------------------------
// Kernel T: transpose x[b][t][i] -> g_xt[t][i][b]. 32x32 tiles.
// Reads coalesced over i, writes coalesced over b.
// ---------------------------------------------------------------------------
__global__ __launch_bounds__(256)
void transpose_x_kernel(const float* __restrict__ x) {
    __shared__ float tile[32][33];
    const int tx = threadIdx.x;          // 0..31
    const int ty = threadIdx.y;          // 0..7
    const int i0 = blockIdx.x * 32;
    const int b0 = blockIdx.y * 32;
    const int t  = blockIdx.z;

#pragma unroll
    for (int r = ty; r < 32; r += 8)
        tile[r][tx] = x[(size_t)(b0 + r) * T_ * I_ + (size_t)t * I_ + i0 + tx];
    __syncthreads();
#pragma unroll
    for (int r = ty; r < 32; r += 8)
        g_xt[t][i0 + r][b0 + tx] = tile[tx][r];
}

// ---------------------------------------------------------------------------
// Kernel S: fused persistent scan. 128 blocks x 256 threads, 1 block/SM.
// Block (bh, cg): batches [bh*32,+32), cols [cg*16,+16).
// Lane l = k4*8 + cgl*4 + bg (k4: 4-way k split, cgl: col half, bg: 8-batch
// group); warp w: k in [w*128,+128). Lane register tile: 8b x 8c (32 f32x2).
//
// Per step tau:
//   1. xw-kloop: W_t (smem) x g_xt[tau] -> acc  [NO dependency on barrier]
//   2. shfl + smem reduce -> xw (+bW) kept in owner-thread registers
//   3. barrier wait (h_{tau-1} visible)
//   4. h-kloop: U_t (smem) x g_ht[(tau-1)&1] -> acc
//   5. reduce -> h = tanh(xw + acc + bU); store g_ht[tau&1] + C_f
//   6. sync; arrive (release next step ASAP); coalesced out1 store
// xw work fills the barrier slack; xw never touches global memory.
// ---------------------------------------------------------------------------
#define KT_STRIDE 20
#define KT_FLOATS (H_ * KT_STRIDE)                  // 20480 floats = 80 KB
#define RED_OFF   (2 * KT_FLOATS)
#define RED_FLOATS (8 * 512)                        // 16 KB
#define CF_OFF    (RED_OFF + RED_FLOATS)
#define SCAN_SMEM ((CF_OFF + 512) * sizeof(float))  // ~178.5 KB

__global__ __launch_bounds__(256, 1)
void scan_kernel(float* __restrict__ out, const float* __restrict__ U,
                 const float* __restrict__ bU, const float* __restrict__ W,
                 const float* __restrict__ bW) {
    extern __shared__ float smem[];
    float* U_t = smem;                  // [1024][20] (16 used)
    float* W_t = smem + KT_FLOATS;      // [1024][20]
    float* red = smem + RED_OFF;        // [8][512]   [w][c*32+b]
    float* C_f = smem + CF_OFF;         // [16][32]

    const int tid = threadIdx.x;
    const int l   = tid & 31;
    const int w   = tid >> 5;
    const int bh  = blockIdx.x & 1;
    const int cg  = blockIdx.x >> 1;          // 0..63
    const int k4  = l >> 3;
    const int cgl = (l >> 2) & 1;
    const int bg  = l & 3;
    const int kbase = w * 128 + k4 * 32;

    // epilogue mappings
    const int c7 = tid >> 4;                  // 0..15 (owner col)
    const int b7 = (tid & 15) * 2;            // 0..30 (owner batch pair)
    const int b9 = tid >> 3;                  // 0..31 (store batch)
    const int c9 = (tid & 7) * 2;             // 0..14 (store col pair)

    // one-time: transpose U and W slices into smem
    for (int idx = tid; idx < 16 * H_; idx += 256) {
        int c = idx >> 10;
        int k = idx & (H_ - 1);
        U_t[k * KT_STRIDE + c] = U[(size_t)(cg * 16 + c) * H_ + k];
        W_t[k * KT_STRIDE + c] = W[(size_t)(cg * 16 + c) * I_ + k];
    }
    const float bUc = bU[cg * 16 + c7];
    const float bWc = bW[cg * 16 + c7];
    __syncthreads();

    const float* urow0 = U_t + kbase * KT_STRIDE + cgl * 8;
    const float* wrow0 = W_t + kbase * KT_STRIDE + cgl * 8;
    const int bB = bh * 32 + bg * 8;          // k-loop batch base
    const int n9  = cg * 16 + c9;
    const int bg9 = bh * 32 + b9;
    float* o9 = out + (size_t)bg9 * T_ * H_ + n9;

    ull acc[8][4];
    unsigned my_gen = 0;
    float xw0_r, xw1_r;

    // ======================= tau = 0 prologue ==============================
    // xw_0 = W x[:,0,:] + bW ; h_0 = tanh(xw_0)
    {
#pragma unroll
        for (int c = 0; c < 8; ++c)
#pragma unroll
            for (int p = 0; p < 4; ++p) acc[c][p] = 0ull;
        const float* xrow = &g_xt[0][kbase][bB];
#pragma unroll 8
        for (int i = 0; i < 32; ++i) {
            const ulonglong2* hp = (const ulonglong2*)(xrow + i * B_);
            ulonglong2 hA = __ldcg(hp);
            ulonglong2 hB = __ldcg(hp + 1);
            const float* up = wrow0 + i * KT_STRIDE;
            float4 u0 = *(const float4*)up;
            float4 u1 = *(const float4*)(up + 4);
            float uf[8] = {u0.x, u0.y, u0.z, u0.w, u1.x, u1.y, u1.z, u1.w};
#pragma unroll
            for (int c = 0; c < 8; ++c) {
                ull s = splat2(uf[c]);
                acc[c][0] = ffma2(hA.x, s, acc[c][0]);
                acc[c][1] = ffma2(hA.y, s, acc[c][1]);
                acc[c][2] = ffma2(hB.x, s, acc[c][2]);
                acc[c][3] = ffma2(hB.y, s, acc[c][3]);
            }
        }
#pragma unroll
        for (int c = 0; c < 8; ++c)
#pragma unroll
            for (int p = 0; p < 4; ++p) {
                acc[c][p] = fadd2(acc[c][p], __shfl_xor_sync(0xffffffffu, acc[c][p], 8));
                acc[c][p] = fadd2(acc[c][p], __shfl_xor_sync(0xffffffffu, acc[c][p], 16));
            }
        if (l < 8) {
            float* rw = red + w * 512;
#pragma unroll
            for (int c = 0; c < 8; ++c)
#pragma unroll
                for (int p = 0; p < 4; ++p)
                    *(ull*)&rw[(cgl * 8 + c) * 32 + bg * 8 + 2 * p] = acc[c][p];
        }
        __syncthreads();
        float s0 = 0.f, s1 = 0.f;
#pragma unroll
        for (int w8 = 0; w8 < 8; ++w8) {
            float2 v = *(const float2*)&red[w8 * 512 + c7 * 32 + b7];
            s0 += v.x; s1 += v.y;
        }
        float h0 = tanhf(s0 + bWc);
        float h1 = tanhf(s1 + bWc);
        int n = cg * 16 + c7;
        int b0 = bh * 32 + b7;
        *(float2*)&g_ht[0][n][b0] = make_float2(h0, h1);
        C_f[c7 * 32 + b7]     = h0;
        C_f[c7 * 32 + b7 + 1] = h1;
        __syncthreads();
        // arrive (release step 1)
        if (tid == 0) {
            __threadfence();
            my_gen = g_gen[bh];
            if (atomicAdd(&g_cnt[bh], 1u) == GROUP_BLOCKS - 1) {
                atomicExch(&g_cnt[bh], 0u);
                __threadfence();
                g_gen[bh] = my_gen + 1;
            }
        }
        // coalesced out1 tau=0 store
        float2 o = make_float2(C_f[c9 * 32 + b9], C_f[(c9 + 1) * 32 + b9]);
        *(float2*)o9 = o;
    }

    // ======================= main loop tau = 1..511 ========================
    for (int tau = 1; tau < T_; ++tau) {
        // ---- phase X: xw_tau = W x[:,tau,:]  (no barrier dependency) ----
#pragma unroll
        for (int c = 0; c < 8; ++c)
#pragma unroll
            for (int p = 0; p < 4; ++p) acc[c][p] = 0ull;
        {
            const float* xrow = &g_xt[tau][kbase][bB];
#pragma unroll 8
            for (int i = 0; i < 32; ++i) {
                const ulonglong2* hp = (const ulonglong2*)(xrow + i * B_);
                ulonglong2 hA = __ldcg(hp);
                ulonglong2 hB = __ldcg(hp + 1);
                const float* up = wrow0 + i * KT_STRIDE;
                float4 u0 = *(const float4*)up;
                float4 u1 = *(const float4*)(up + 4);
                float uf[8] = {u0.x, u0.y, u0.z, u0.w, u1.x, u1.y, u1.z, u1.w};
#pragma unroll
                for (int c = 0; c < 8; ++c) {
                    ull s = splat2(uf[c]);
                    acc[c][0] = ffma2(hA.x, s, acc[c][0]);
                    acc[c][1] = ffma2(hA.y, s, acc[c][1]);
                    acc[c][2] = ffma2(hB.x, s, acc[c][2]);
                    acc[c][3] = ffma2(hB.y, s, acc[c][3]);
                }
            }
        }
#pragma unroll
        for (int c = 0; c < 8; ++c)
#pragma unroll
            for (int p = 0; p < 4; ++p) {
                acc[c][p] = fadd2(acc[c][p], __shfl_xor_sync(0xffffffffu, acc[c][p], 8));
                acc[c][p] = fadd2(acc[c][p], __shfl_xor_sync(0xffffffffu, acc[c][p], 16));
            }
        if (l < 8) {
            float* rw = red + w * 512;
#pragma unroll
            for (int c = 0; c < 8; ++c)
#pragma unroll
                for (int p = 0; p < 4; ++p)
                    *(ull*)&rw[(cgl * 8 + c) * 32 + bg * 8 + 2 * p] = acc[c][p];
        }
        __syncthreads();
        {
            float s0 = 0.f, s1 = 0.f;
#pragma unroll
            for (int w8 = 0; w8 < 8; ++w8) {
                float2 v = *(const float2*)&red[w8 * 512 + c7 * 32 + b7];
                s0 += v.x; s1 += v.y;
            }
            xw0_r = s0 + bWc;
            xw1_r = s1 + bWc;
        }

        // ---- barrier wait: h_{tau-1} visible ----
        if (tid == 0) {
            while (g_gen[bh] == my_gen) { }
            __threadfence();
        }
        __syncthreads();   // also protects red reuse below

        // ---- phase H: U h_{tau-1} ----
#pragma unroll
        for (int c = 0; c < 8; ++c)
#pragma unroll
            for (int p = 0; p < 4; ++p) acc[c][p] = 0ull;
        {
            const float* hrow = &g_ht[(tau - 1) & 1][kbase][bB];
#pragma unroll 8
            for (int i = 0; i < 32; ++i) {
                const ulonglong2* hp = (const ulonglong2*)(hrow + i * B_);
                ulonglong2 hA = __ldcg(hp);
                ulonglong2 hB = __ldcg(hp + 1);
                const float* up = urow0 + i * KT_STRIDE;
                float4 u0 = *(const float4*)up;
                float4 u1 = *(const float4*)(up + 4);
                float uf[8] = {u0.x, u0.y, u0.z, u0.w, u1.x, u1.y, u1.z, u1.w};
#pragma unroll
                for (int c = 0; c < 8; ++c) {
                    ull s = splat2(uf[c]);
                    acc[c][0] = ffma2(hA.x, s, acc[c][0]);
                    acc[c][1] = ffma2(hA.y, s, acc[c][1]);
                    acc[c][2] = ffma2(hB.x, s, acc[c][2]);
                    acc[c][3] = ffma2(hB.y, s, acc[c][3]);
                }
            }
        }
#pragma unroll
        for (int c = 0; c < 8; ++c)
#pragma unroll
            for (int p = 0; p < 4; ++p) {
                acc[c][p] = fadd2(acc[c][p], __shfl_xor_sync(0xffffffffu, acc[c][p], 8));
                acc[c][p] = fadd2(acc[c][p], __shfl_xor_sync(0xffffffffu, acc[c][p], 16));
            }
        if (l < 8) {
            float* rw = red + w * 512;
#pragma unroll
            for (int c = 0; c < 8; ++c)
#pragma unroll
                for (int p = 0; p < 4; ++p)
                    *(ull*)&rw[(cgl * 8 + c) * 32 + bg * 8 + 2 * p] = acc[c][p];
        }
        __syncthreads();
        {
            float s0 = 0.f, s1 = 0.f;
#pragma unroll
            for (int w8 = 0; w8 < 8; ++w8) {
                float2 v = *(const float2*)&red[w8 * 512 + c7 * 32 + b7];
                s0 += v.x; s1 += v.y;
            }
            float h0 = tanhf(xw0_r + s0 + bUc);
            float h1 = tanhf(xw1_r + s1 + bUc);
            int n  = cg * 16 + c7;
            int b0 = bh * 32 + b7;
            *(float2*)&g_ht[tau & 1][n][b0] = make_float2(h0, h1);
            C_f[c7 * 32 + b7]     = h0;
            C_f[c7 * 32 + b7 + 1] = h1;
        }
        __syncthreads();   // g_ht + C_f visible block-wide

        // ---- arrive ASAP (next step's enabling event) ----
        if (tau < T_ - 1) {
            if (tid == 0) {
                __threadfence();
                my_gen = g_gen[bh];
                if (atomicAdd(&g_cnt[bh], 1u) == GROUP_BLOCKS - 1) {
                    atomicExch(&g_cnt[bh], 0u);
                    __threadfence();
                    g_gen[bh] = my_gen + 1;
                }
            }
        }

        // ---- coalesced out1 (+out2) store, off the critical path ----
        float2 o = make_float2(C_f[c9 * 32 + b9], C_f[(c9 + 1) * 32 + b9]);
        *(float2*)(o9 + (size_t)tau * H_) = o;
        if (tau == T_ - 1)
            *(float2*)(out + (size_t)M_ * H_ + (size_t)bg9 * H_ + n9) = o;
    }
}

// ---------------------------------------------------------------------------
// Launch
// ---------------------------------------------------------------------------
extern "C" void kernel_launch(void* const* d_in, const int* in_sizes, int n_in,
                              void* d_out, int out_size) {
    const float* x  = (const float*)d_in[0];   // [B,T,I]
    const float* W  = (const float*)d_in[1];   // [H,I]
    const float* bW = (const float*)d_in[2];   // [H]
    const float* U  = (const float*)d_in[3];   // [H,H]
    const float* bU = (const float*)d_in[4];   // [H]
    float* out = (float*)d_out;                // out1 [B*T*H] ++ out2 [B*H]

    dim3 tb(32, 8);
    dim3 tg(I_ / 32, B_ / 32, T_);   // (32, 2, 512)
    transpose_x_kernel<<<tg, tb>>>(x);

    cudaFuncSetAttribute(scan_kernel, cudaFuncAttributeMaxDynamicSharedMemorySize,
                         (int)SCAN_SMEM);
    scan_kernel<<<SCAN_BLOCKS, 256, SCAN_SMEM>>>(out, U, bU, W, bW);
}

// round 11
// speedup vs baseline: 2.5956x; 1.0581x over previous
#include <cuda_runtime.h>
#include <math.h>

#define B_  64
#define T_  512
#define I_  1024
#define H_  1024
#define M_  (B_*T_)

typedef unsigned long long ull;

// ---------------------------------------------------------------------------
// f32x2 packed helpers (sm_103a FFMA2/FADD2 — only reachable via PTX)
// ---------------------------------------------------------------------------
__device__ __forceinline__ ull ffma2(ull a, ull b, ull c) {
    ull d;
    asm("fma.rn.f32x2 %0, %1, %2, %3;" : "=l"(d) : "l"(a), "l"(b), "l"(c));
    return d;
}
__device__ __forceinline__ ull fadd2(ull a, ull b) {
    ull d;
    asm("add.rn.f32x2 %0, %1, %2;" : "=l"(d) : "l"(a), "l"(b));
    return d;
}
__device__ __forceinline__ ull splat2(float x) {
    ull r;
    asm("mov.b64 %0, {%1, %1};" : "=l"(r) : "f"(x));
    return r;
}

// ---------------------------------------------------------------------------
// Scratch (device globals — no allocation allowed)
// ---------------------------------------------------------------------------
__device__ float g_xt[T_][I_][B_];     // transposed x: [t][k][b]  (128 MB)
__device__ float g_ht[2][H_][B_];      // transposed h double buffer [buf][k][b]
__device__ unsigned g_cnt[2];          // per-batch-half barrier counters
__device__ volatile unsigned g_gen[2]; // monotonic generations (replay-safe)

#define SCAN_BLOCKS  128
#define GROUP_BLOCKS 64

// ---------------------------------------------------------------------------
// Kernel T: transpose x[b][t][i] -> g_xt[t][i][b]. 32x32 tiles.
// ---------------------------------------------------------------------------
__global__ __launch_bounds__(256)
void transpose_x_kernel(const float* __restrict__ x) {
    __shared__ float tile[32][33];
    const int tx = threadIdx.x;
    const int ty = threadIdx.y;
    const int i0 = blockIdx.x * 32;
    const int b0 = blockIdx.y * 32;
    const int t  = blockIdx.z;

#pragma unroll
    for (int r = ty; r < 32; r += 8)
        tile[r][tx] = x[(size_t)(b0 + r) * T_ * I_ + (size_t)t * I_ + i0 + tx];
    __syncthreads();
#pragma unroll
    for (int r = ty; r < 32; r += 8)
        g_xt[t][i0 + r][b0 + tx] = tile[tx][r];
}

// ---------------------------------------------------------------------------
// Kernel S: fused persistent scan with MERGED accumulation.
// 128 blocks x 256 threads, 1 block/SM. Block (bh, cg): batches [bh*32,+32),
// cols [cg*16,+16). Lane l = k4*8 + cgl*4 + bg; warp w: k in [w*128,+128).
// Lane register tile: 8b x 8c = 32 f32x2 accumulators.
//
// Per step tau (ONE reduction per step):
//   1. zero acc; X-kloop: acc += W_t * g_xt[tau]   [no barrier dependency]
//   2. barrier wait (h_{tau-1} visible)
//   3. H-kloop: acc += U_t * g_ht[(tau-1)&1]       [same k-partition]
//   4. single reduce (shfl x2, smem partials, 8-way sum)
//   5. h = tanh(sum + bW + bU); store g_ht[tau&1] + C_f
//   6. sync; arrive; coalesced out1 store
// ---------------------------------------------------------------------------
#define KT_STRIDE 20
#define KT_FLOATS (H_ * KT_STRIDE)                  // 80 KB
#define RED_OFF   (2 * KT_FLOATS)
#define RED_FLOATS (8 * 512)                        // 16 KB
#define CF_OFF    (RED_OFF + RED_FLOATS)
#define SCAN_SMEM ((CF_OFF + 512) * sizeof(float))  // ~178.5 KB

__global__ __launch_bounds__(256, 1)
void scan_kernel(float* __restrict__ out, const float* __restrict__ U,
                 const float* __restrict__ bU, const float* __restrict__ W,
                 const float* __restrict__ bW) {
    extern __shared__ float smem[];
    float* U_t = smem;                  // [1024][20] (16 used)
    float* W_t = smem + KT_FLOATS;      // [1024][20]
    float* red = smem + RED_OFF;        // [8][512]   [w][c*32+b]
    float* C_f = smem + CF_OFF;         // [16][32]

    const int tid = threadIdx.x;
    const int l   = tid & 31;
    const int w   = tid >> 5;
    const int bh  = blockIdx.x & 1;
    const int cg  = blockIdx.x >> 1;          // 0..63
    const int k4  = l >> 3;
    const int cgl = (l >> 2) & 1;
    const int bg  = l & 3;
    const int kbase = w * 128 + k4 * 32;

    // epilogue mappings
    const int c7 = tid >> 4;                  // 0..15 (owner col)
    const int b7 = (tid & 15) * 2;            // 0..30 (owner batch pair)
    const int b9 = tid >> 3;                  // 0..31 (store batch)
    const int c9 = (tid & 7) * 2;             // 0..14 (store col pair)

    // one-time: transpose U and W slices into smem
    for (int idx = tid; idx < 16 * H_; idx += 256) {
        int c = idx >> 10;
        int k = idx & (H_ - 1);
        U_t[k * KT_STRIDE + c] = U[(size_t)(cg * 16 + c) * H_ + k];
        W_t[k * KT_STRIDE + c] = W[(size_t)(cg * 16 + c) * I_ + k];
    }
    const float bWc = bW[cg * 16 + c7];
    const float bSc = bWc + bU[cg * 16 + c7];   // combined bias for tau>=1
    __syncthreads();

    const float* urow0 = U_t + kbase * KT_STRIDE + cgl * 8;
    const float* wrow0 = W_t + kbase * KT_STRIDE + cgl * 8;
    const int bB  = bh * 32 + bg * 8;
    const int n9  = cg * 16 + c9;
    const int bg9 = bh * 32 + b9;
    float* o9 = out + (size_t)bg9 * T_ * H_ + n9;

    ull acc[8][4];
    unsigned my_gen = 0;

// ---- macro: accumulate one k-slice matvec into acc ------------------------
#define KLOOP(SRCROW, UWROW)                                                  \
    {                                                                         \
        const float* srow_ = (SRCROW);                                        \
        const float* mrow_ = (UWROW);                                         \
        _Pragma("unroll 8")                                                   \
        for (int i = 0; i < 32; ++i) {                                        \
            const ulonglong2* hp = (const ulonglong2*)(srow_ + i * B_);       \
            ulonglong2 hA = __ldcg(hp);                                       \
            ulonglong2 hB = __ldcg(hp + 1);                                   \
            const float* up = mrow_ + i * KT_STRIDE;                          \
            float4 u0 = *(const float4*)up;                                   \
            float4 u1 = *(const float4*)(up + 4);                             \
            float uf[8] = {u0.x, u0.y, u0.z, u0.w, u1.x, u1.y, u1.z, u1.w};   \
            _Pragma("unroll")                                                 \
            for (int c = 0; c < 8; ++c) {                                     \
                ull s = splat2(uf[c]);                                        \
                acc[c][0] = ffma2(hA.x, s, acc[c][0]);                        \
                acc[c][1] = ffma2(hA.y, s, acc[c][1]);                        \
                acc[c][2] = ffma2(hB.x, s, acc[c][2]);                        \
                acc[c][3] = ffma2(hB.y, s, acc[c][3]);                        \
            }                                                                 \
        }                                                                     \
    }

// ---- macro: in-warp butterfly + smem partials -----------------------------
#define REDUCE_TO_SMEM()                                                      \
    {                                                                         \
        _Pragma("unroll")                                                     \
        for (int c = 0; c < 8; ++c)                                           \
            _Pragma("unroll")                                                 \
            for (int p = 0; p < 4; ++p) {                                     \
                acc[c][p] = fadd2(acc[c][p],                                  \
                    __shfl_xor_sync(0xffffffffu, acc[c][p], 8));              \
                acc[c][p] = fadd2(acc[c][p],                                  \
                    __shfl_xor_sync(0xffffffffu, acc[c][p], 16));             \
            }                                                                 \
        if (l < 8) {                                                          \
            float* rw = red + w * 512;                                        \
            _Pragma("unroll")                                                 \
            for (int c = 0; c < 8; ++c)                                       \
                _Pragma("unroll")                                             \
                for (int p = 0; p < 4; ++p)                                   \
                    *(ull*)&rw[(cgl * 8 + c) * 32 + bg * 8 + 2 * p] =         \
                        acc[c][p];                                            \
        }                                                                     \
    }

#define ARRIVE()                                                              \
    if (tid == 0) {                                                           \
        __threadfence();                                                      \
        my_gen = g_gen[bh];                                                   \
        if (atomicAdd(&g_cnt[bh], 1u) == GROUP_BLOCKS - 1) {                  \
            atomicExch(&g_cnt[bh], 0u);                                       \
            __threadfence();                                                  \
            g_gen[bh] = my_gen + 1;                                           \
        }                                                                     \
    }

    // ======================= tau = 0 prologue ==============================
    {
#pragma unroll
        for (int c = 0; c < 8; ++c)
#pragma unroll
            for (int p = 0; p < 4; ++p) acc[c][p] = 0ull;
        KLOOP(&g_xt[0][kbase][bB], wrow0);
        REDUCE_TO_SMEM();
        __syncthreads();
        float s0 = 0.f, s1 = 0.f;
#pragma unroll
        for (int w8 = 0; w8 < 8; ++w8) {
            float2 v = *(const float2*)&red[w8 * 512 + c7 * 32 + b7];
            s0 += v.x; s1 += v.y;
        }
        float h0 = tanhf(s0 + bWc);
        float h1 = tanhf(s1 + bWc);
        int n  = cg * 16 + c7;
        int b0 = bh * 32 + b7;
        *(float2*)&g_ht[0][n][b0] = make_float2(h0, h1);
        C_f[c7 * 32 + b7]     = h0;
        C_f[c7 * 32 + b7 + 1] = h1;
        __syncthreads();
        ARRIVE();
        float2 o = make_float2(C_f[c9 * 32 + b9], C_f[(c9 + 1) * 32 + b9]);
        *(float2*)o9 = o;
    }

    // ======================= main loop tau = 1..511 ========================
    for (int tau = 1; tau < T_; ++tau) {
        // phase X: acc = W x[:,tau,:] partials (no barrier dependency)
#pragma unroll
        for (int c = 0; c < 8; ++c)
#pragma unroll
            for (int p = 0; p < 4; ++p) acc[c][p] = 0ull;
        KLOOP(&g_xt[tau][kbase][bB], wrow0);

        // barrier wait: h_{tau-1} visible
        if (tid == 0) {
            while (g_gen[bh] == my_gen) { }
            __threadfence();
        }
        __syncthreads();                       // S1 (also protects red reuse)

        // phase H: acc += U h_{tau-1} (same k-partition -> merged reduce)
        KLOOP(&g_ht[(tau - 1) & 1][kbase][bB], urow0);

        REDUCE_TO_SMEM();
        __syncthreads();                       // S2

        {
            float s0 = 0.f, s1 = 0.f;
#pragma unroll
            for (int w8 = 0; w8 < 8; ++w8) {
                float2 v = *(const float2*)&red[w8 * 512 + c7 * 32 + b7];
                s0 += v.x; s1 += v.y;
            }
            float h0 = tanhf(s0 + bSc);
            float h1 = tanhf(s1 + bSc);
            int n  = cg * 16 + c7;
            int b0 = bh * 32 + b7;
            *(float2*)&g_ht[tau & 1][n][b0] = make_float2(h0, h1);
            C_f[c7 * 32 + b7]     = h0;
            C_f[c7 * 32 + b7 + 1] = h1;
        }
        __syncthreads();                       // S3: g_ht + C_f visible

        // arrive ASAP (next step's enabling event)
        if (tau < T_ - 1) { ARRIVE(); }

        // coalesced out1 (+out2) store, off the critical path
        float2 o = make_float2(C_f[c9 * 32 + b9], C_f[(c9 + 1) * 32 + b9]);
        *(float2*)(o9 + (size_t)tau * H_) = o;
        if (tau == T_ - 1)
            *(float2*)(out + (size_t)M_ * H_ + (size_t)bg9 * H_ + n9) = o;
    }

#undef KLOOP
#undef REDUCE_TO_SMEM
#undef ARRIVE
}

// ---------------------------------------------------------------------------
// Launch
// ---------------------------------------------------------------------------
extern "C" void kernel_launch(void* const* d_in, const int* in_sizes, int n_in,
                              void* d_out, int out_size) {
    const float* x  = (const float*)d_in[0];   // [B,T,I]
    const float* W  = (const float*)d_in[1];   // [H,I]
    const float* bW = (const float*)d_in[2];   // [H]
    const float* U  = (const float*)d_in[3];   // [H,H]
    const float* bU = (const float*)d_in[4];   // [H]
    float* out = (float*)d_out;                // out1 [B*T*H] ++ out2 [B*H]

    dim3 tb(32, 8);
    dim3 tg(I_ / 32, B_ / 32, T_);   // (32, 2, 512)
    transpose_x_kernel<<<tg, tb>>>(x);

    cudaFuncSetAttribute(scan_kernel, cudaFuncAttributeMaxDynamicSharedMemorySize,
                         (int)SCAN_SMEM);
    scan_kernel<<<SCAN_BLOCKS, 256, SCAN_SMEM>>>(out, U, bU, W, bW);
}